// round 2
// baseline (speedup 1.0000x reference)
#include <cuda_runtime.h>
#include <math.h>

typedef unsigned long long ull;

// ---------------------------------------------------------------------------
// Problem constants
// ---------------------------------------------------------------------------
namespace {
constexpr int TT = 128, BB = 32;
constexpr int POS_E = 64, WORD_E = 512, POS_H = 256, WORD_H = 1024;
constexpr int POS_V = 45, WORD_V = 32000;
constexpr int NTOK = TT * BB;  // 4096

// ---------------------------------------------------------------------------
// Device scratch (static globals; no allocation allowed)
// ---------------------------------------------------------------------------
__device__ float g_p_embT[POS_E * NTOK];           // transposed [E][tok] 1 MB
__device__ float g_w_embT[WORD_E * NTOK];          // 8 MB
__device__ float g_pouts[NTOK * POS_H];            // pos hidden per step 4 MB
__device__ float g_wouts[NTOK * WORD_H];           // word layer-1 hidden 16 MB
__device__ float g_woutsT[WORD_H * NTOK];          // transposed copy 16 MB
__device__ float g_wh0[2][BB * WORD_H];            // word layer-0 hidden ping-pong
__device__ float g_pc[2][BB * POS_H];
__device__ float g_wc0[2][BB * WORD_H];
__device__ float g_wc1[2][BB * WORD_H];
__device__ float g_zero[BB * WORD_H];
__device__ float g_gpart[8][BB * 4 * WORD_H];      // K-chunk partial gate sums 4 MB
__device__ float g_wmidT[WORD_E * NTOK];           // 8 MB (transposed wmid)
__device__ float g_pre_p[NTOK * 4 * POS_H];        // precomputed emb@Wih (pos) 16 MB
__device__ float g_pre_w0[NTOK * 4 * WORD_H];      // precomputed emb@Wih (word0) 64 MB
__device__ int   g_cnt[TT * 3 * 32];               // completion counters
}  // namespace

// ---------------------------------------------------------------------------
// f32x2 packed-FMA helpers (ptxas never emits FFMA2 from C++; PTX only)
// ---------------------------------------------------------------------------
__device__ __forceinline__ ull pack2(float lo, float hi) {
    ull r; asm("mov.b64 %0, {%1,%2};" : "=l"(r) : "f"(lo), "f"(hi)); return r;
}
__device__ __forceinline__ ull dup2(float v) { return pack2(v, v); }
__device__ __forceinline__ void fma2(ull& d, ull a, ull b) {
    asm("fma.rn.f32x2 %0, %1, %2, %0;" : "+l"(d) : "l"(a), "l"(b));
}
__device__ __forceinline__ void unpack2(ull v, float& lo, float& hi) {
    asm("mov.b64 {%0,%1}, %2;" : "=f"(lo), "=f"(hi) : "l"(v));
}
__device__ __forceinline__ float sigm(float x) { return 1.f / (1.f + expf(-x)); }

// ---------------------------------------------------------------------------
// Init + embedding gather (transposed layout for downstream GEMMs)
// ---------------------------------------------------------------------------
__global__ void zero_init_kernel() {
    int i = blockIdx.x * blockDim.x + threadIdx.x;
    if (i < BB * WORD_H) {
        g_zero[i]   = 0.f;
        g_wc0[0][i] = 0.f;
        g_wc1[0][i] = 0.f;
    }
    if (i < BB * POS_H) g_pc[0][i] = 0.f;
    if (i < TT * 3 * 32) g_cnt[i] = 0;
}

__global__ void gather_kernel(const int* __restrict__ pos, const int* __restrict__ word,
                              const float* __restrict__ posW, const float* __restrict__ wordW) {
    int j = blockIdx.x * blockDim.x + threadIdx.x;
    if (j < WORD_E * NTOK) {
        int d = j / NTOK, tok = j - d * NTOK;
        g_w_embT[j] = wordW[(size_t)word[tok] * WORD_E + d];
    }
    if (j < POS_E * NTOK) {
        int d = j / NTOK, tok = j - d * NTOK;
        g_p_embT[j] = posW[(size_t)pos[tok] * POS_E + d];
    }
}

// ---------------------------------------------------------------------------
// Fused LSTM cell: K-chunked partial GEMM, last-arriving block per h-tile
// reduces partials + precomputed emb part + biases and applies gates.
//   grid = (H/32 tiles, nchunks). Block 256 threads.
//   Compute: 32 batch rows x 32 h x 4 gates, f32x2-paired over batch rows.
// ---------------------------------------------------------------------------
struct Chunk { const float* x; const float* W; int ldx; int ldw; int koff; int klen; };
struct Chunks8 { Chunk c[8]; };

__global__ __launch_bounds__(256) void lstm_cell_kernel(
    Chunks8 ch8, int H,
    const float* __restrict__ bih, const float* __restrict__ bhh,
    const float* __restrict__ pre,            // [BB][4H] slice for this t, or null
    const float* __restrict__ cin, float* __restrict__ cout,
    float* __restrict__ hout, float* __restrict__ houtT,  // houtT pre-offset by tok base
    int* __restrict__ cnt, float* __restrict__ gpart) {
    __shared__ float xs[32][33];
    __shared__ float ws[128][33];
    const Chunk ch = ch8.c[blockIdx.y];
    float* outp = gpart + (size_t)blockIdx.y * (BB * 4 * WORD_H);
    const int tid = threadIdx.x;
    const int rg = tid & 7;    // rows rg + 8j
    const int hl = tid >> 3;   // 0..31
    const int hBase = blockIdx.x * 32;
    const int H4 = 4 * H;

    ull accP[4][2];
#pragma unroll
    for (int g = 0; g < 4; g++) { accP[g][0] = 0ull; accP[g][1] = 0ull; }

    for (int kb = 0; kb < ch.klen; kb += 32) {
#pragma unroll
        for (int it = 0; it < 4; it++) {
            int idx = tid + it * 256;
            int row = idx >> 5, k = idx & 31;
            xs[row][k] = ch.x[(size_t)row * ch.ldx + kb + k];
        }
#pragma unroll
        for (int it = 0; it < 16; it++) {
            int idx = tid + it * 256;
            int tr = idx >> 5, k = idx & 31;
            int g = tr >> 5, hh = tr & 31;
            ws[tr][k] = ch.W[(size_t)(g * H + hBase + hh) * ch.ldw + ch.koff + kb + k];
        }
        __syncthreads();
#pragma unroll
        for (int k = 0; k < 32; k++) {
            ull xp0 = pack2(xs[rg][k], xs[rg + 8][k]);
            ull xp1 = pack2(xs[rg + 16][k], xs[rg + 24][k]);
#pragma unroll
            for (int g = 0; g < 4; g++) {
                ull wd = dup2(ws[g * 32 + hl][k]);
                fma2(accP[g][0], wd, xp0);
                fma2(accP[g][1], wd, xp1);
            }
        }
        __syncthreads();
    }
    // write partial tile
#pragma unroll
    for (int g = 0; g < 4; g++) {
        float a0, a1, a2, a3;
        unpack2(accP[g][0], a0, a1);
        unpack2(accP[g][1], a2, a3);
        size_t base = (size_t)g * H + hBase + hl;
        outp[(size_t)(rg +  0) * H4 + base] = a0;
        outp[(size_t)(rg +  8) * H4 + base] = a1;
        outp[(size_t)(rg + 16) * H4 + base] = a2;
        outp[(size_t)(rg + 24) * H4 + base] = a3;
    }
    __threadfence();
    __shared__ int isLast;
    if (tid == 0)
        isLast = (atomicAdd(cnt + blockIdx.x, 1) == (int)gridDim.y - 1);
    __syncthreads();
    if (!isLast) return;
    __threadfence();

    // ---- reduce + gate for this 32h tile, all 32 batch rows ----
    const int hl2 = tid & 31;
    const int h = hBase + hl2;
    const int r0 = tid >> 5;  // 0..7
    const int ny = gridDim.y;
    float bb0 = bih[0 * H + h] + bhh[0 * H + h];
    float bb1 = bih[1 * H + h] + bhh[1 * H + h];
    float bb2 = bih[2 * H + h] + bhh[2 * H + h];
    float bb3 = bih[3 * H + h] + bhh[3 * H + h];
#pragma unroll
    for (int j = 0; j < 4; j++) {
        int r = r0 + 8 * j;
        float gi = bb0, gf = bb1, gg = bb2, go = bb3;
        for (int s = 0; s < ny; s++) {
            const float* p = gpart + (size_t)s * (BB * 4 * WORD_H) + (size_t)r * H4;
            gi += p[0 * H + h];
            gf += p[1 * H + h];
            gg += p[2 * H + h];
            go += p[3 * H + h];
        }
        if (pre) {
            const float* q = pre + (size_t)r * H4;
            gi += q[0 * H + h];
            gf += q[1 * H + h];
            gg += q[2 * H + h];
            go += q[3 * H + h];
        }
        float i = sigm(gi), f = sigm(gf), g = tanhf(gg), o = sigm(go);
        float c2 = f * cin[(size_t)r * H + h] + i * g;
        float h2 = o * tanhf(c2);
        cout[(size_t)r * H + h] = c2;
        hout[(size_t)r * H + h] = h2;
        if (houtT) houtT[(size_t)h * NTOK + r] = h2;
    }
}

// ---------------------------------------------------------------------------
// f32x2 GEMM: C[m,n] = sum_k AT[k,m] * W[n,k] + bias[n]
//   A given TRANSPOSED (AT[K][M], ld = M). 128x128 tile, 256 threads,
//   8x8 micro-tile, accumulators paired over adjacent columns (FFMA2).
//   Optionally writes C [M][N] and/or CT [N][M].
// ---------------------------------------------------------------------------
__global__ __launch_bounds__(256) void gemm_t_kernel(
    const float* __restrict__ AT, int M,
    const float* __restrict__ W, int ldw, const float* __restrict__ bias,
    float* __restrict__ C, float* __restrict__ CT, int N, int K) {
    __shared__ float As[32][128];       // [k][m]
    __shared__ float Ws[32][132];       // [k][n] (+4 pad, rows 16B-aligned)
    const int tid = threadIdx.x;
    const int rt = tid & 15;            // row group: rows rt + 16*jj
    const int ct = tid >> 4;            // col group: cols ct*8 .. ct*8+7
    const int rBase = blockIdx.y * 128, cBase = blockIdx.x * 128;

    ull acc[8][4];
#pragma unroll
    for (int jj = 0; jj < 8; jj++)
#pragma unroll
        for (int p = 0; p < 4; p++) acc[jj][p] = 0ull;

    for (int kb = 0; kb < K; kb += 32) {
        // As: coalesced float4 from AT (already transposed)
#pragma unroll
        for (int it = 0; it < 4; it++) {
            int flat = tid + it * 256;
            int k = flat >> 5, m4 = flat & 31;
            float4 v = *(const float4*)&AT[(size_t)(kb + k) * M + rBase + m4 * 4];
            *(float4*)&As[k][m4 * 4] = v;
        }
        // Ws: read W rows (float4 along k), transpose-store into [k][n]
#pragma unroll
        for (int it = 0; it < 4; it++) {
            int flat = tid + it * 256;
            int n = flat >> 3, k4 = flat & 7;
            float4 v = *(const float4*)&W[(size_t)(cBase + n) * ldw + kb + k4 * 4];
            Ws[k4 * 4 + 0][n] = v.x;
            Ws[k4 * 4 + 1][n] = v.y;
            Ws[k4 * 4 + 2][n] = v.z;
            Ws[k4 * 4 + 3][n] = v.w;
        }
        __syncthreads();
#pragma unroll
        for (int k = 0; k < 32; k++) {
            ull xd[8];
#pragma unroll
            for (int jj = 0; jj < 8; jj++) xd[jj] = dup2(As[k][rt + 16 * jj]);
            const ulonglong2* wp = (const ulonglong2*)&Ws[k][ct * 8];
            ulonglong2 wa = wp[0];
            ulonglong2 wb = wp[1];
#pragma unroll
            for (int jj = 0; jj < 8; jj++) {
                fma2(acc[jj][0], xd[jj], wa.x);
                fma2(acc[jj][1], xd[jj], wa.y);
                fma2(acc[jj][2], xd[jj], wb.x);
                fma2(acc[jj][3], xd[jj], wb.y);
            }
        }
        __syncthreads();
    }
    // epilogue
    float bcol[8];
#pragma unroll
    for (int q = 0; q < 8; q++) bcol[q] = bias ? bias[cBase + ct * 8 + q] : 0.f;
#pragma unroll
    for (int jj = 0; jj < 8; jj++) {
        int m = rBase + rt + 16 * jj;
        float v[8];
#pragma unroll
        for (int p = 0; p < 4; p++) unpack2(acc[jj][p], v[2 * p], v[2 * p + 1]);
#pragma unroll
        for (int q = 0; q < 8; q++) v[q] += bcol[q];
        if (C) {
            float4* dst = (float4*)&C[(size_t)m * N + cBase + ct * 8];
            dst[0] = make_float4(v[0], v[1], v[2], v[3]);
            dst[1] = make_float4(v[4], v[5], v[6], v[7]);
        }
        if (CT) {
#pragma unroll
            for (int q = 0; q < 8; q++)
                CT[(size_t)(cBase + ct * 8 + q) * M + m] = v[q];
        }
    }
}

// ---------------------------------------------------------------------------
// pos projection + log-softmax (one warp per (t,b) row; V=45, K=256)
// ---------------------------------------------------------------------------
__global__ void pos_proj_kernel(const float* __restrict__ Wp, const float* __restrict__ bp,
                                float* __restrict__ out) {
    const int row = blockIdx.x;
    const int lane = threadIdx.x;
    const bool has1 = (lane + 32 < POS_V);
    const float* x = g_pouts + (size_t)row * POS_H;
    float s0 = bp[lane];
    float s1 = has1 ? bp[lane + 32] : -INFINITY;
    const float* w0 = Wp + (size_t)lane * POS_H;
    const float* w1 = Wp + (size_t)(has1 ? lane + 32 : 0) * POS_H;
    for (int k = 0; k < POS_H; k++) {
        float xv = x[k];
        s0 = fmaf(xv, w0[k], s0);
        if (has1) s1 = fmaf(xv, w1[k], s1);
    }
    float m = fmaxf(s0, s1);
#pragma unroll
    for (int o = 16; o; o >>= 1) m = fmaxf(m, __shfl_xor_sync(0xffffffffu, m, o));
    float e = expf(s0 - m) + (has1 ? expf(s1 - m) : 0.f);
#pragma unroll
    for (int o = 16; o; o >>= 1) e += __shfl_xor_sync(0xffffffffu, e, o);
    float ls = m + logf(e);
    out[(size_t)row * POS_V + lane] = s0 - ls;
    if (has1) out[(size_t)row * POS_V + lane + 32] = s1 - ls;
}

// ---------------------------------------------------------------------------
// word log-softmax in place over 32000 (one block per row)
// ---------------------------------------------------------------------------
__global__ void word_softmax_kernel(float* __restrict__ logits) {
    __shared__ float red[8];
    const int row = blockIdx.x;
    float* p = logits + (size_t)row * WORD_V;
    const int tid = threadIdx.x;  // 256
    float m = -INFINITY;
    for (int i = tid; i < WORD_V; i += 256) m = fmaxf(m, p[i]);
#pragma unroll
    for (int o = 16; o; o >>= 1) m = fmaxf(m, __shfl_xor_sync(0xffffffffu, m, o));
    if ((tid & 31) == 0) red[tid >> 5] = m;
    __syncthreads();
    float M = red[0];
#pragma unroll
    for (int w = 1; w < 8; w++) M = fmaxf(M, red[w]);
    __syncthreads();
    float s = 0.f;
    for (int i = tid; i < WORD_V; i += 256) s += expf(p[i] - M);
#pragma unroll
    for (int o = 16; o; o >>= 1) s += __shfl_xor_sync(0xffffffffu, s, o);
    if ((tid & 31) == 0) red[tid >> 5] = s;
    __syncthreads();
    float S = 0.f;
#pragma unroll
    for (int w = 0; w < 8; w++) S += red[w];
    float ls = M + logf(S);
    for (int i = tid; i < WORD_V; i += 256) p[i] -= ls;
}

// ---------------------------------------------------------------------------
// Host side
// ---------------------------------------------------------------------------
static void add_seg(Chunks8& cc, int& n, const float* x, int ldx,
                    const float* W, int ldw, int koff, int klen) {
    while (klen > 0) {
        int c = klen > 256 ? 256 : klen;
        cc.c[n].x = x; cc.c[n].W = W; cc.c[n].ldx = ldx; cc.c[n].ldw = ldw;
        cc.c[n].koff = koff; cc.c[n].klen = c;
        n++;
        x += c; koff += c; klen -= c;
    }
}

extern "C" void kernel_launch(void* const* d_in, const int* in_sizes, int n_in,
                              void* d_out, int out_size) {
    (void)in_sizes; (void)n_in; (void)out_size;
    const int*   pos        = (const int*)d_in[0];
    const int*   word       = (const int*)d_in[1];
    const float* pos_emb_W  = (const float*)d_in[2];
    const float* word_emb_W = (const float*)d_in[3];
    const float* pos_Wih    = (const float*)d_in[4];
    const float* pos_Whh    = (const float*)d_in[5];
    const float* pos_bih    = (const float*)d_in[6];
    const float* pos_bhh    = (const float*)d_in[7];
    const float* w0_Wih     = (const float*)d_in[8];
    const float* w0_Whh     = (const float*)d_in[9];
    const float* w0_bih     = (const float*)d_in[10];
    const float* w0_bhh     = (const float*)d_in[11];
    const float* w1_Wih     = (const float*)d_in[12];
    const float* w1_Whh     = (const float*)d_in[13];
    const float* w1_bih     = (const float*)d_in[14];
    const float* w1_bhh     = (const float*)d_in[15];
    const float* pos_proj_W = (const float*)d_in[16];
    const float* pos_proj_b = (const float*)d_in[17];
    const float* wp1_W      = (const float*)d_in[18];
    const float* wp1_b      = (const float*)d_in[19];
    const float* wp2_b      = (const float*)d_in[20];
    float* out = (float*)d_out;

    float *p_embT, *w_embT, *pouts, *wouts, *woutsT, *wh0, *pc, *wc0, *wc1;
    float *zerobuf, *gpart, *wmidT, *pre_p, *pre_w0;
    int* cnt;
    cudaGetSymbolAddress((void**)&p_embT, g_p_embT);
    cudaGetSymbolAddress((void**)&w_embT, g_w_embT);
    cudaGetSymbolAddress((void**)&pouts, g_pouts);
    cudaGetSymbolAddress((void**)&wouts, g_wouts);
    cudaGetSymbolAddress((void**)&woutsT, g_woutsT);
    cudaGetSymbolAddress((void**)&wh0, g_wh0);
    cudaGetSymbolAddress((void**)&pc, g_pc);
    cudaGetSymbolAddress((void**)&wc0, g_wc0);
    cudaGetSymbolAddress((void**)&wc1, g_wc1);
    cudaGetSymbolAddress((void**)&zerobuf, g_zero);
    cudaGetSymbolAddress((void**)&gpart, g_gpart);
    cudaGetSymbolAddress((void**)&wmidT, g_wmidT);
    cudaGetSymbolAddress((void**)&pre_p, g_pre_p);
    cudaGetSymbolAddress((void**)&pre_w0, g_pre_w0);
    cudaGetSymbolAddress((void**)&cnt, g_cnt);

    zero_init_kernel<<<128, 256>>>();
    gather_kernel<<<(WORD_E * NTOK + 255) / 256, 256>>>(pos, word, pos_emb_W, word_emb_W);

    // Precompute emb@Wih parts for all timesteps (removed from sequential path)
    gemm_t_kernel<<<dim3(4 * POS_H / 128, NTOK / 128), 256>>>(
        p_embT, NTOK, pos_Wih, POS_E + WORD_H, nullptr, pre_p, nullptr, 4 * POS_H, POS_E);
    gemm_t_kernel<<<dim3(4 * WORD_H / 128, NTOK / 128), 256>>>(
        w_embT, NTOK, w0_Wih, WORD_E + POS_H, nullptr, pre_w0, nullptr, 4 * WORD_H, WORD_E);

    for (int t = 0; t < TT; t++) {
        const float* p_h_prev  = t ? pouts + (size_t)(t - 1) * BB * POS_H : zerobuf;
        const float* w1_h_prev = t ? wouts + (size_t)(t - 1) * BB * WORD_H : zerobuf;
        const float* wh0_prev  = t ? wh0 + (size_t)((t - 1) & 1) * BB * WORD_H : zerobuf;
        float* wh0_cur  = wh0 + (size_t)(t & 1) * BB * WORD_H;
        float* p_h_cur  = pouts + (size_t)t * BB * POS_H;
        float* w1_h_cur = wouts + (size_t)t * BB * WORD_H;
        const float* pc_in   = pc  + (size_t)(t & 1) * BB * POS_H;
        float*       pc_out  = pc  + (size_t)((t + 1) & 1) * BB * POS_H;
        const float* wc0_in  = wc0 + (size_t)(t & 1) * BB * WORD_H;
        float*       wc0_out = wc0 + (size_t)((t + 1) & 1) * BB * WORD_H;
        const float* wc1_in  = wc1 + (size_t)(t & 1) * BB * WORD_H;
        float*       wc1_out = wc1 + (size_t)((t + 1) & 1) * BB * WORD_H;

        // ---- pos cell (emb part precomputed): seq K = 1024 + 256 ----
        {
            Chunks8 cc; int n = 0;
            add_seg(cc, n, w1_h_prev, WORD_H, pos_Wih, POS_E + WORD_H, POS_E, WORD_H);
            add_seg(cc, n, p_h_prev,  POS_H,  pos_Whh, POS_H,          0,     POS_H);
            lstm_cell_kernel<<<dim3(POS_H / 32, n), 256>>>(
                cc, POS_H, pos_bih, pos_bhh, pre_p + (size_t)t * BB * 4 * POS_H,
                pc_in, pc_out, p_h_cur, nullptr, cnt + (t * 3 + 0) * 32, gpart);
        }
        // ---- word layer 0 (emb part precomputed): seq K = 256 + 1024 ----
        {
            Chunks8 cc; int n = 0;
            add_seg(cc, n, p_h_cur,  POS_H,  w0_Wih, WORD_E + POS_H, WORD_E, POS_H);
            add_seg(cc, n, wh0_prev, WORD_H, w0_Whh, WORD_H,         0,      WORD_H);
            lstm_cell_kernel<<<dim3(WORD_H / 32, n), 256>>>(
                cc, WORD_H, w0_bih, w0_bhh, pre_w0 + (size_t)t * BB * 4 * WORD_H,
                wc0_in, wc0_out, wh0_cur, nullptr, cnt + (t * 3 + 1) * 32, gpart);
        }
        // ---- word layer 1: seq K = 1024 + 1024 ----
        {
            Chunks8 cc; int n = 0;
            add_seg(cc, n, wh0_cur,   WORD_H, w1_Wih, WORD_H, 0, WORD_H);
            add_seg(cc, n, w1_h_prev, WORD_H, w1_Whh, WORD_H, 0, WORD_H);
            lstm_cell_kernel<<<dim3(WORD_H / 32, n), 256>>>(
                cc, WORD_H, w1_bih, w1_bhh, nullptr,
                wc1_in, wc1_out, w1_h_cur, woutsT + (size_t)t * BB,
                cnt + (t * 3 + 2) * 32, gpart);
        }
    }

    // ---- pos projection + log-softmax -> out[0 : NTOK*POS_V] ----
    pos_proj_kernel<<<NTOK, 32>>>(pos_proj_W, pos_proj_b, out);

    // ---- word head: wmidT = (wouts @ wp1_W^T + b)^T ; logits = wmid @ word_emb_W^T + b ----
    gemm_t_kernel<<<dim3(WORD_E / 128, NTOK / 128), 256>>>(
        woutsT, NTOK, wp1_W, WORD_H, wp1_b, nullptr, wmidT, WORD_E, WORD_H);
    float* wlp = out + (size_t)NTOK * POS_V;
    gemm_t_kernel<<<dim3(WORD_V / 128, NTOK / 128), 256>>>(
        wmidT, NTOK, word_emb_W, WORD_E, wp2_b, wlp, nullptr, WORD_V, WORD_E);
    word_softmax_kernel<<<NTOK, 256>>>(wlp);
}